// round 2
// baseline (speedup 1.0000x reference)
#include <cuda_runtime.h>
#include <cuda_fp16.h>
#include <stdint.h>

#define SEQ 2048
#define HD 128
#define BM 128
#define BN 64
#define NTHREADS 256
#define KV_TILES (SEQ / BN)   // 32
#define Q_TILES  (SEQ / BM)   // 16
#define BH 32
#define SOFTMAX_SCALE 0.08838834764831845f

// Swizzled smem layout: rows of 256 bytes (128 half), 16-byte chunks,
// chunk index XORed with (row & 7) -> conflict-free ldmatrix over 8-row groups.
__device__ __forceinline__ uint32_t swz_off(int row, int ch) {
    return (uint32_t)((row << 8) + ((ch ^ (row & 7)) << 4));
}

__device__ __forceinline__ uint32_t pack_h2(float lo, float hi) {
    __half2 h = __floats2half2_rn(lo, hi);
    return *reinterpret_cast<uint32_t*>(&h);
}

__device__ __forceinline__ void ldmatrix_x4(uint32_t& r0, uint32_t& r1, uint32_t& r2, uint32_t& r3,
                                            uint32_t addr) {
    asm volatile("ldmatrix.sync.aligned.m8n8.x4.shared.b16 {%0,%1,%2,%3}, [%4];\n"
                 : "=r"(r0), "=r"(r1), "=r"(r2), "=r"(r3) : "r"(addr));
}

__device__ __forceinline__ void ldmatrix_x4_trans(uint32_t& r0, uint32_t& r1, uint32_t& r2, uint32_t& r3,
                                                  uint32_t addr) {
    asm volatile("ldmatrix.sync.aligned.m8n8.x4.trans.shared.b16 {%0,%1,%2,%3}, [%4];\n"
                 : "=r"(r0), "=r"(r1), "=r"(r2), "=r"(r3) : "r"(addr));
}

__device__ __forceinline__ void mma_f16(float& c0, float& c1, float& c2, float& c3,
                                        uint32_t a0, uint32_t a1, uint32_t a2, uint32_t a3,
                                        uint32_t b0, uint32_t b1) {
    asm volatile("mma.sync.aligned.m16n8k16.row.col.f32.f16.f16.f32 "
                 "{%0,%1,%2,%3}, {%4,%5,%6,%7}, {%8,%9}, {%0,%1,%2,%3};\n"
                 : "+f"(c0), "+f"(c1), "+f"(c2), "+f"(c3)
                 : "r"(a0), "r"(a1), "r"(a2), "r"(a3), "r"(b0), "r"(b1));
}

__global__ void __launch_bounds__(NTHREADS, 1)
fa_fwd_kernel(const float* __restrict__ Qg_, const float* __restrict__ Kg_,
              const float* __restrict__ Vg_, float* __restrict__ Og_) {
    // 32 KB: K tile (64 rows x 256B) + V tile (64 rows x 256B).
    // Q (128 rows x 256B) is staged across the full 32 KB before the KV loop.
    __shared__ __align__(16) unsigned char sm[2 * 64 * 256];
    unsigned char* smK = sm;
    unsigned char* smV = sm + 16384;

    const int tid  = threadIdx.x;
    const int warp = tid >> 5;
    const int lane = tid & 31;
    const int qtile = blockIdx.x;
    const int bh    = blockIdx.y;

    const size_t base = (size_t)bh * SEQ * HD;
    const float* Qg = Qg_ + base + (size_t)qtile * BM * HD;
    const float* Kg = Kg_ + base;
    const float* Vg = Vg_ + base;
    float*       Og = Og_ + base + (size_t)qtile * BM * HD;

    const uint32_t smBase = (uint32_t)__cvta_generic_to_shared(sm);
    const uint32_t smKb = smBase;
    const uint32_t smVb = smBase + 16384;

    // ---------------- Stage Q (pre-scaled) as f16 into full 32 KB smem ----------------
    #pragma unroll
    for (int it = 0; it < 8; it++) {
        int id = tid + it * NTHREADS;          // 0..2047 -> 128 rows x 16 chunks
        int row = id >> 4, ch = id & 15;
        const float4* p = reinterpret_cast<const float4*>(Qg + row * HD + ch * 8);
        float4 u = p[0], v = p[1];
        uint4 w;
        w.x = pack_h2(u.x * SOFTMAX_SCALE, u.y * SOFTMAX_SCALE);
        w.y = pack_h2(u.z * SOFTMAX_SCALE, u.w * SOFTMAX_SCALE);
        w.z = pack_h2(v.x * SOFTMAX_SCALE, v.y * SOFTMAX_SCALE);
        w.w = pack_h2(v.z * SOFTMAX_SCALE, v.w * SOFTMAX_SCALE);
        *reinterpret_cast<uint4*>(sm + swz_off(row, ch)) = w;
    }
    __syncthreads();

    // Q A-fragments: warp owns rows [16*warp, 16*warp+16), 8 k-steps of 16.
    uint32_t qa[8][4];
    {
        int r = 16 * warp + (lane & 15);
        int csel = lane >> 4;                  // k half select
        #pragma unroll
        for (int kk = 0; kk < 8; kk++) {
            uint32_t addr = smBase + swz_off(r, 2 * kk + csel);
            ldmatrix_x4(qa[kk][0], qa[kk][1], qa[kk][2], qa[kk][3], addr);
        }
    }
    __syncthreads();   // before overwriting smem with K/V tiles

    // ---------------- Online-softmax state ----------------
    float o[16][4];
    #pragma unroll
    for (int j = 0; j < 16; j++) { o[j][0] = 0.f; o[j][1] = 0.f; o[j][2] = 0.f; o[j][3] = 0.f; }
    float m0 = -1e30f, m1 = -1e30f;   // running row maxima (two rows per lane)
    float l0 = 0.f,    l1 = 0.f;      // lane-local partial row sums

    const int r8  = lane & 7;
    const int sel = lane >> 3;

    for (int t = 0; t < KV_TILES; t++) {
        const float* Kt = Kg + (size_t)t * BN * HD;
        const float* Vt = Vg + (size_t)t * BN * HD;

        // -------- load + convert K and V tiles (fp32 -> f16, swizzled) --------
        #pragma unroll
        for (int it = 0; it < 4; it++) {
            int id = tid + it * NTHREADS;      // 0..1023 -> 64 rows x 16 chunks
            int row = id >> 4, ch = id & 15;
            uint32_t so = swz_off(row, ch);
            {
                const float4* p = reinterpret_cast<const float4*>(Kt + row * HD + ch * 8);
                float4 u = p[0], v = p[1];
                uint4 w;
                w.x = pack_h2(u.x, u.y); w.y = pack_h2(u.z, u.w);
                w.z = pack_h2(v.x, v.y); w.w = pack_h2(v.z, v.w);
                *reinterpret_cast<uint4*>(smK + so) = w;
            }
            {
                const float4* p = reinterpret_cast<const float4*>(Vt + row * HD + ch * 8);
                float4 u = p[0], v = p[1];
                uint4 w;
                w.x = pack_h2(u.x, u.y); w.y = pack_h2(u.z, u.w);
                w.z = pack_h2(v.x, v.y); w.w = pack_h2(v.z, v.w);
                *reinterpret_cast<uint4*>(smV + so) = w;
            }
        }
        __syncthreads();

        // -------- S = (Q*scale) @ K^T  (16 x 64 per warp, fp32 accum) --------
        float s[8][4];
        #pragma unroll
        for (int j = 0; j < 8; j++) { s[j][0] = 0.f; s[j][1] = 0.f; s[j][2] = 0.f; s[j][3] = 0.f; }

        #pragma unroll
        for (int kk = 0; kk < 8; kk++) {
            #pragma unroll
            for (int j = 0; j < 8; j += 2) {
                // x4 ldmatrix: m0,m1 -> B-frag for n-tile j; m2,m3 -> n-tile j+1
                uint32_t b0, b1, b2, b3;
                uint32_t addr = smKb + swz_off(8 * j + ((sel >> 1) << 3) + r8,
                                               2 * kk + (sel & 1));
                ldmatrix_x4(b0, b1, b2, b3, addr);
                mma_f16(s[j][0],   s[j][1],   s[j][2],   s[j][3],
                        qa[kk][0], qa[kk][1], qa[kk][2], qa[kk][3], b0, b1);
                mma_f16(s[j+1][0], s[j+1][1], s[j+1][2], s[j+1][3],
                        qa[kk][0], qa[kk][1], qa[kk][2], qa[kk][3], b2, b3);
            }
        }

        // -------- online softmax (rows l>>2 and (l>>2)+8, quad-reduced) --------
        float tm0 = -1e30f, tm1 = -1e30f;
        #pragma unroll
        for (int j = 0; j < 8; j++) {
            tm0 = fmaxf(tm0, fmaxf(s[j][0], s[j][1]));
            tm1 = fmaxf(tm1, fmaxf(s[j][2], s[j][3]));
        }
        tm0 = fmaxf(tm0, __shfl_xor_sync(0xffffffffu, tm0, 1));
        tm0 = fmaxf(tm0, __shfl_xor_sync(0xffffffffu, tm0, 2));
        tm1 = fmaxf(tm1, __shfl_xor_sync(0xffffffffu, tm1, 1));
        tm1 = fmaxf(tm1, __shfl_xor_sync(0xffffffffu, tm1, 2));

        float mn0 = fmaxf(m0, tm0), mn1 = fmaxf(m1, tm1);
        float al0 = __expf(m0 - mn0), al1 = __expf(m1 - mn1);

        float sum0 = 0.f, sum1 = 0.f;
        #pragma unroll
        for (int j = 0; j < 8; j++) {
            s[j][0] = __expf(s[j][0] - mn0); sum0 += s[j][0];
            s[j][1] = __expf(s[j][1] - mn0); sum0 += s[j][1];
            s[j][2] = __expf(s[j][2] - mn1); sum1 += s[j][2];
            s[j][3] = __expf(s[j][3] - mn1); sum1 += s[j][3];
        }
        l0 = l0 * al0 + sum0;
        l1 = l1 * al1 + sum1;
        m0 = mn0; m1 = mn1;

        #pragma unroll
        for (int j = 0; j < 16; j++) {
            o[j][0] *= al0; o[j][1] *= al0;
            o[j][2] *= al1; o[j][3] *= al1;
        }

        // -------- O += P @ V  (P from S registers, V via ldmatrix.trans) --------
        #pragma unroll
        for (int kkp = 0; kkp < 4; kkp++) {
            uint32_t a0 = pack_h2(s[2*kkp][0],   s[2*kkp][1]);
            uint32_t a1 = pack_h2(s[2*kkp][2],   s[2*kkp][3]);
            uint32_t a2 = pack_h2(s[2*kkp+1][0], s[2*kkp+1][1]);
            uint32_t a3 = pack_h2(s[2*kkp+1][2], s[2*kkp+1][3]);
            #pragma unroll
            for (int jt = 0; jt < 16; jt += 2) {
                uint32_t b0, b1, b2, b3;
                uint32_t addr = smVb + swz_off(16 * kkp + ((sel & 1) << 3) + r8,
                                               jt + (sel >> 1));
                ldmatrix_x4_trans(b0, b1, b2, b3, addr);
                mma_f16(o[jt][0],   o[jt][1],   o[jt][2],   o[jt][3],   a0, a1, a2, a3, b0, b1);
                mma_f16(o[jt+1][0], o[jt+1][1], o[jt+1][2], o[jt+1][3], a0, a1, a2, a3, b2, b3);
            }
        }
        __syncthreads();   // protect smem before next tile's overwrite
    }

    // ---------------- finalize: reduce l across quad, normalize, store ----------------
    l0 += __shfl_xor_sync(0xffffffffu, l0, 1);
    l0 += __shfl_xor_sync(0xffffffffu, l0, 2);
    l1 += __shfl_xor_sync(0xffffffffu, l1, 1);
    l1 += __shfl_xor_sync(0xffffffffu, l1, 2);
    float inv0 = 1.f / l0, inv1 = 1.f / l1;

    int row0 = 16 * warp + (lane >> 2);
    int col0 = (lane & 3) * 2;
    #pragma unroll
    for (int jt = 0; jt < 16; jt++) {
        float2 v0 = make_float2(o[jt][0] * inv0, o[jt][1] * inv0);
        float2 v1 = make_float2(o[jt][2] * inv1, o[jt][3] * inv1);
        *reinterpret_cast<float2*>(Og + (size_t)row0 * HD + 8 * jt + col0) = v0;
        *reinterpret_cast<float2*>(Og + (size_t)(row0 + 8) * HD + 8 * jt + col0) = v1;
    }
}

extern "C" void kernel_launch(void* const* d_in, const int* in_sizes, int n_in,
                              void* d_out, int out_size) {
    const float* Q = (const float*)d_in[0];
    const float* K = (const float*)d_in[1];
    const float* V = (const float*)d_in[2];
    float* O = (float*)d_out;
    dim3 grid(Q_TILES, BH);
    fa_fwd_kernel<<<grid, NTHREADS>>>(Q, K, V, O);
}

// round 4
// speedup vs baseline: 1.0811x; 1.0811x over previous
#include <cuda_runtime.h>
#include <cuda_fp16.h>
#include <stdint.h>

#define SEQ 2048
#define HD 128
#define BM 128
#define BN 64
#define NTHREADS 256
#define KV_TILES (SEQ / BN)   // 32
#define Q_TILES  (SEQ / BM)   // 16
#define BH 32
// softmax scale with log2(e) folded in: P = exp2(S_scaled - m_scaled)
#define QSCALE (0.08838834764831845f * 1.4426950408889634f)

// smem layout (dynamic, 96KB): Q 32KB | K0 16KB | K1 16KB | V0 16KB | V1 16KB
#define SM_Q   0
#define SM_K0  32768
#define SM_V0  65536
#define SM_TOTAL 98304

// Swizzled smem layout: rows of 256 bytes (128 half), 16-byte chunks,
// chunk index XORed with (row & 7) -> conflict-free ldmatrix over 8-row groups.
__device__ __forceinline__ uint32_t swz_off(int row, int ch) {
    return (uint32_t)((row << 8) + ((ch ^ (row & 7)) << 4));
}

__device__ __forceinline__ uint32_t pack_h2(float lo, float hi) {
    __half2 h = __floats2half2_rn(lo, hi);
    return *reinterpret_cast<uint32_t*>(&h);
}

__device__ __forceinline__ void ldmatrix_x4(uint32_t& r0, uint32_t& r1, uint32_t& r2, uint32_t& r3,
                                            uint32_t addr) {
    asm volatile("ldmatrix.sync.aligned.m8n8.x4.shared.b16 {%0,%1,%2,%3}, [%4];\n"
                 : "=r"(r0), "=r"(r1), "=r"(r2), "=r"(r3) : "r"(addr));
}

__device__ __forceinline__ void ldmatrix_x4_trans(uint32_t& r0, uint32_t& r1, uint32_t& r2, uint32_t& r3,
                                                  uint32_t addr) {
    asm volatile("ldmatrix.sync.aligned.m8n8.x4.trans.shared.b16 {%0,%1,%2,%3}, [%4];\n"
                 : "=r"(r0), "=r"(r1), "=r"(r2), "=r"(r3) : "r"(addr));
}

__device__ __forceinline__ void mma_f16(float& c0, float& c1, float& c2, float& c3,
                                        uint32_t a0, uint32_t a1, uint32_t a2, uint32_t a3,
                                        uint32_t b0, uint32_t b1) {
    asm volatile("mma.sync.aligned.m16n8k16.row.col.f32.f16.f16.f32 "
                 "{%0,%1,%2,%3}, {%4,%5,%6,%7}, {%8,%9}, {%0,%1,%2,%3};\n"
                 : "+f"(c0), "+f"(c1), "+f"(c2), "+f"(c3)
                 : "r"(a0), "r"(a1), "r"(a2), "r"(a3), "r"(b0), "r"(b1));
}

__global__ void __launch_bounds__(NTHREADS, 1)
fa_fwd_kernel(const float* __restrict__ Qg_, const float* __restrict__ Kg_,
              const float* __restrict__ Vg_, float* __restrict__ Og_) {
    extern __shared__ __align__(16) unsigned char sm[];

    const int tid  = threadIdx.x;
    const int warp = tid >> 5;
    const int lane = tid & 31;
    const int qtile = blockIdx.x;
    const int bh    = blockIdx.y;

    const size_t base = (size_t)bh * SEQ * HD;
    const float* Qg = Qg_ + base + (size_t)qtile * BM * HD;
    const float* Kg = Kg_ + base;
    const float* Vg = Vg_ + base;
    float*       Og = Og_ + base + (size_t)qtile * BM * HD;

    const uint32_t smBase = (uint32_t)__cvta_generic_to_shared(sm);

    // ---------------- Stage Q (pre-scaled, incl. log2e) as f16 ----------------
    #pragma unroll
    for (int it = 0; it < 8; it++) {
        int id = tid + it * NTHREADS;          // 0..2047 -> 128 rows x 16 chunks
        int row = id >> 4, ch = id & 15;
        const float4* p = reinterpret_cast<const float4*>(Qg + row * HD + ch * 8);
        float4 u = p[0], v = p[1];
        uint4 w;
        w.x = pack_h2(u.x * QSCALE, u.y * QSCALE);
        w.y = pack_h2(u.z * QSCALE, u.w * QSCALE);
        w.z = pack_h2(v.x * QSCALE, v.y * QSCALE);
        w.w = pack_h2(v.z * QSCALE, v.w * QSCALE);
        *reinterpret_cast<uint4*>(sm + SM_Q + swz_off(row, ch)) = w;
    }

    // ---------------- Stage K[0], V[0] into buffer 0 ----------------
    #pragma unroll
    for (int it = 0; it < 4; it++) {
        int id = tid + it * NTHREADS;          // 0..1023 -> 64 rows x 16 chunks
        int row = id >> 4, ch = id & 15;
        uint32_t so = swz_off(row, ch);
        {
            const float4* p = reinterpret_cast<const float4*>(Kg + row * HD + ch * 8);
            float4 u = p[0], v = p[1];
            uint4 w;
            w.x = pack_h2(u.x, u.y); w.y = pack_h2(u.z, u.w);
            w.z = pack_h2(v.x, v.y); w.w = pack_h2(v.z, v.w);
            *reinterpret_cast<uint4*>(sm + SM_K0 + so) = w;
        }
        {
            const float4* p = reinterpret_cast<const float4*>(Vg + row * HD + ch * 8);
            float4 u = p[0], v = p[1];
            uint4 w;
            w.x = pack_h2(u.x, u.y); w.y = pack_h2(u.z, u.w);
            w.z = pack_h2(v.x, v.y); w.w = pack_h2(v.z, v.w);
            *reinterpret_cast<uint4*>(sm + SM_V0 + so) = w;
        }
    }
    __syncthreads();

    // ---------------- Online-softmax state ----------------
    float o[16][4];
    #pragma unroll
    for (int j = 0; j < 16; j++) { o[j][0] = 0.f; o[j][1] = 0.f; o[j][2] = 0.f; o[j][3] = 0.f; }
    float m0 = -1e30f, m1 = -1e30f;
    float l0 = 0.f,    l1 = 0.f;

    const int r8  = lane & 7;
    const int sel = lane >> 3;
    const int qrow = 16 * warp + (lane & 15);
    const int qcsel = lane >> 4;

    for (int t = 0; t < KV_TILES; t++) {
        const int cur = t & 1;
        const int nxt = cur ^ 1;
        const bool pf = (t + 1 < KV_TILES);
        const uint32_t smKcur = smBase + SM_K0 + cur * 16384;
        const uint32_t smVcur = smBase + SM_V0 + cur * 16384;

        // -------- prefetch K[t+1] into registers (latency hidden by QK) --------
        float4 kp[4][2];
        if (pf) {
            const float* Kt1 = Kg + (size_t)(t + 1) * BN * HD;
            #pragma unroll
            for (int it = 0; it < 4; it++) {
                int id = tid + it * NTHREADS;
                int row = id >> 4, ch = id & 15;
                const float4* p = reinterpret_cast<const float4*>(Kt1 + row * HD + ch * 8);
                kp[it][0] = p[0]; kp[it][1] = p[1];
            }
        }

        // -------- S = (Q*scale) @ K^T  (16 x 64 per warp, fp32 accum) --------
        float s[8][4];
        #pragma unroll
        for (int j = 0; j < 8; j++) { s[j][0] = 0.f; s[j][1] = 0.f; s[j][2] = 0.f; s[j][3] = 0.f; }

        #pragma unroll
        for (int kk = 0; kk < 8; kk++) {
            uint32_t qa0, qa1, qa2, qa3;
            ldmatrix_x4(qa0, qa1, qa2, qa3,
                        smBase + SM_Q + swz_off(qrow, 2 * kk + qcsel));
            #pragma unroll
            for (int j = 0; j < 8; j += 2) {
                uint32_t b0, b1, b2, b3;
                uint32_t addr = smKcur + swz_off(8 * j + ((sel >> 1) << 3) + r8,
                                                 2 * kk + (sel & 1));
                ldmatrix_x4(b0, b1, b2, b3, addr);
                mma_f16(s[j][0],   s[j][1],   s[j][2],   s[j][3],   qa0, qa1, qa2, qa3, b0, b1);
                mma_f16(s[j+1][0], s[j+1][1], s[j+1][2], s[j+1][3], qa0, qa1, qa2, qa3, b2, b3);
            }
        }

        // -------- store K[t+1] into the other buffer (frees kp regs) --------
        if (pf) {
            #pragma unroll
            for (int it = 0; it < 4; it++) {
                int id = tid + it * NTHREADS;
                int row = id >> 4, ch = id & 15;
                uint4 w;
                w.x = pack_h2(kp[it][0].x, kp[it][0].y);
                w.y = pack_h2(kp[it][0].z, kp[it][0].w);
                w.z = pack_h2(kp[it][1].x, kp[it][1].y);
                w.w = pack_h2(kp[it][1].z, kp[it][1].w);
                *reinterpret_cast<uint4*>(sm + SM_K0 + nxt * 16384 + swz_off(row, ch)) = w;
            }
        }

        // -------- prefetch V[t+1] (latency hidden by softmax + PV) --------
        float4 vp[4][2];
        if (pf) {
            const float* Vt1 = Vg + (size_t)(t + 1) * BN * HD;
            #pragma unroll
            for (int it = 0; it < 4; it++) {
                int id = tid + it * NTHREADS;
                int row = id >> 4, ch = id & 15;
                const float4* p = reinterpret_cast<const float4*>(Vt1 + row * HD + ch * 8);
                vp[it][0] = p[0]; vp[it][1] = p[1];
            }
        }

        // -------- online softmax (base-2; rows l>>2 and +8, quad-reduced) --------
        float tm0 = -1e30f, tm1 = -1e30f;
        #pragma unroll
        for (int j = 0; j < 8; j++) {
            tm0 = fmaxf(tm0, fmaxf(s[j][0], s[j][1]));
            tm1 = fmaxf(tm1, fmaxf(s[j][2], s[j][3]));
        }
        tm0 = fmaxf(tm0, __shfl_xor_sync(0xffffffffu, tm0, 1));
        tm0 = fmaxf(tm0, __shfl_xor_sync(0xffffffffu, tm0, 2));
        tm1 = fmaxf(tm1, __shfl_xor_sync(0xffffffffu, tm1, 1));
        tm1 = fmaxf(tm1, __shfl_xor_sync(0xffffffffu, tm1, 2));

        float mn0 = fmaxf(m0, tm0), mn1 = fmaxf(m1, tm1);
        float al0 = exp2f(m0 - mn0), al1 = exp2f(m1 - mn1);

        float sum0 = 0.f, sum1 = 0.f;
        #pragma unroll
        for (int j = 0; j < 8; j++) {
            s[j][0] = exp2f(s[j][0] - mn0); sum0 += s[j][0];
            s[j][1] = exp2f(s[j][1] - mn0); sum0 += s[j][1];
            s[j][2] = exp2f(s[j][2] - mn1); sum1 += s[j][2];
            s[j][3] = exp2f(s[j][3] - mn1); sum1 += s[j][3];
        }
        l0 = l0 * al0 + sum0;
        l1 = l1 * al1 + sum1;

        // skip the O rescale when no row max in the warp changed (al == 1 exactly)
        bool chg = (mn0 != m0) || (mn1 != m1);
        if (__any_sync(0xffffffffu, chg)) {
            #pragma unroll
            for (int j = 0; j < 16; j++) {
                o[j][0] *= al0; o[j][1] *= al0;
                o[j][2] *= al1; o[j][3] *= al1;
            }
        }
        m0 = mn0; m1 = mn1;

        // -------- O += P @ V  (P from S registers, V via ldmatrix.trans) --------
        #pragma unroll
        for (int kkp = 0; kkp < 4; kkp++) {
            uint32_t a0 = pack_h2(s[2*kkp][0],   s[2*kkp][1]);
            uint32_t a1 = pack_h2(s[2*kkp][2],   s[2*kkp][3]);
            uint32_t a2 = pack_h2(s[2*kkp+1][0], s[2*kkp+1][1]);
            uint32_t a3 = pack_h2(s[2*kkp+1][2], s[2*kkp+1][3]);
            #pragma unroll
            for (int jt = 0; jt < 16; jt += 2) {
                uint32_t b0, b1, b2, b3;
                uint32_t addr = smVcur + swz_off(16 * kkp + ((sel & 1) << 3) + r8,
                                                 jt + (sel >> 1));
                ldmatrix_x4_trans(b0, b1, b2, b3, addr);
                mma_f16(o[jt][0],   o[jt][1],   o[jt][2],   o[jt][3],   a0, a1, a2, a3, b0, b1);
                mma_f16(o[jt+1][0], o[jt+1][1], o[jt+1][2], o[jt+1][3], a0, a1, a2, a3, b2, b3);
            }
        }

        // -------- store V[t+1] into the other buffer --------
        if (pf) {
            #pragma unroll
            for (int it = 0; it < 4; it++) {
                int id = tid + it * NTHREADS;
                int row = id >> 4, ch = id & 15;
                uint4 w;
                w.x = pack_h2(vp[it][0].x, vp[it][0].y);
                w.y = pack_h2(vp[it][0].z, vp[it][0].w);
                w.z = pack_h2(vp[it][1].x, vp[it][1].y);
                w.w = pack_h2(vp[it][1].z, vp[it][1].w);
                *reinterpret_cast<uint4*>(sm + SM_V0 + nxt * 16384 + swz_off(row, ch)) = w;
            }
        }
        __syncthreads();
    }

    // ---------------- finalize: reduce l across quad, normalize, store ----------------
    l0 += __shfl_xor_sync(0xffffffffu, l0, 1);
    l0 += __shfl_xor_sync(0xffffffffu, l0, 2);
    l1 += __shfl_xor_sync(0xffffffffu, l1, 1);
    l1 += __shfl_xor_sync(0xffffffffu, l1, 2);
    float inv0 = 1.f / l0, inv1 = 1.f / l1;

    int row0 = 16 * warp + (lane >> 2);
    int col0 = (lane & 3) * 2;
    #pragma unroll
    for (int jt = 0; jt < 16; jt++) {
        float2 v0 = make_float2(o[jt][0] * inv0, o[jt][1] * inv0);
        float2 v1 = make_float2(o[jt][2] * inv1, o[jt][3] * inv1);
        *reinterpret_cast<float2*>(Og + (size_t)row0 * HD + 8 * jt + col0) = v0;
        *reinterpret_cast<float2*>(Og + (size_t)(row0 + 8) * HD + 8 * jt + col0) = v1;
    }
}

extern "C" void kernel_launch(void* const* d_in, const int* in_sizes, int n_in,
                              void* d_out, int out_size) {
    const float* Q = (const float*)d_in[0];
    const float* K = (const float*)d_in[1];
    const float* V = (const float*)d_in[2];
    float* O = (float*)d_out;
    cudaFuncSetAttribute(fa_fwd_kernel, cudaFuncAttributeMaxDynamicSharedMemorySize, SM_TOTAL);
    dim3 grid(Q_TILES, BH);
    fa_fwd_kernel<<<grid, NTHREADS, SM_TOTAL>>>(Q, K, V, O);
}